// round 6
// baseline (speedup 1.0000x reference)
#include <cuda_runtime.h>
#include <cuda_bf16.h>
#include <cstdint>

#define NN 10240
#define EE 160000

// Scratch (static device globals)
__device__ __nv_bfloat16 g_G[(size_t)NN * 4096];   // G[n][kb][o][ki]: kb=k/8 (16), o (32), ki=k%8 (8)
__device__ float g_hb[NN * 32];
__device__ float g_Bperm[4096 * 32];
__device__ float g_sum_ef[NN * 32];
__device__ float g_sum_tr[NN * 3];
__device__ int   g_cnt[NN];        // row-degree (mean)
__device__ int   g_deg[NN];        // col-degree (sort)
__device__ int   g_cur[NN];        // scatter cursor
__device__ int   g_off[NN + 1];    // col-group start offsets
// sorted edge data (by col)
__device__ int   g_srow[EE];
__device__ float g_sea[(size_t)EE * 8];
__device__ float g_scd[(size_t)EE * 4];

// ---------------- zero ----------------
__global__ void zero_kernel(int N) {
    int i = blockIdx.x * blockDim.x + threadIdx.x;
    if (i < N * 32) g_sum_ef[i] = 0.f;
    if (i < N * 3)  g_sum_tr[i] = 0.f;
    if (i < N) { g_cnt[i] = 0; g_deg[i] = 0; }
}

// ---------------- permute Wk2 for the [kb][o][ki] G layout ----------------
__global__ void bperm_kernel(const float* __restrict__ Wk2) {
    int idx = blockIdx.x * blockDim.x + threadIdx.x;
    if (idx >= 4096 * 32) return;
    int i = idx & 31;
    int c = idx >> 5;
    int kb = c >> 8;
    int o  = (c >> 3) & 31;
    int ki = c & 7;
    int k  = kb * 8 + ki;
    g_Bperm[idx] = Wk2[k * 1024 + i * 32 + o];
}

// ---------------- hb = h @ bk2 ----------------
__global__ void hb_kernel(const float* __restrict__ h, const float* __restrict__ bk2, int N) {
    int warp = threadIdx.x >> 5, lane = threadIdx.x & 31;
    int n = blockIdx.x * 8 + warp;
    if (n >= N) return;
    float hv = h[n * 32 + lane];
    float acc = 0.f;
#pragma unroll
    for (int i = 0; i < 32; i++)
        acc = fmaf(__shfl_sync(0xffffffffu, hv, i), bk2[i * 32 + lane], acc);
    g_hb[n * 32 + lane] = acc;
}

// ---------------- G = H @ Bperm, bf16, 2 cols x 2 nodes per thread ----------------
__global__ __launch_bounds__(256) void g_kernel(const float* __restrict__ h, int N) {
    __shared__ float hs[64 * 32];
    int n0 = blockIdx.x * 64;
    int c0 = (blockIdx.y * 256 + threadIdx.x) * 2;
    int lim = N * 32;
    for (int t = threadIdx.x; t < 64 * 32; t += 256) {
        int gi = n0 * 32 + t;
        hs[t] = (gi < lim) ? h[gi] : 0.f;
    }
    __syncthreads();
    float b0[32], b1[32];
#pragma unroll
    for (int q = 0; q < 8; q++) {
        float4 v0 = *reinterpret_cast<const float4*>(&g_Bperm[(size_t)c0 * 32 + q * 4]);
        float4 v1 = *reinterpret_cast<const float4*>(&g_Bperm[(size_t)(c0 + 1) * 32 + q * 4]);
        b0[q*4+0] = v0.x; b0[q*4+1] = v0.y; b0[q*4+2] = v0.z; b0[q*4+3] = v0.w;
        b1[q*4+0] = v1.x; b1[q*4+1] = v1.y; b1[q*4+2] = v1.z; b1[q*4+3] = v1.w;
    }
    int nmax = min(64, N - n0);
    int nn = 0;
    for (; nn + 1 < nmax; nn += 2) {
        float a0 = 0.f, a1 = 0.f, a2 = 0.f, a3 = 0.f;
#pragma unroll
        for (int q = 0; q < 8; q++) {
            float4 hA = *reinterpret_cast<const float4*>(&hs[nn * 32 + q * 4]);
            float4 hB = *reinterpret_cast<const float4*>(&hs[(nn + 1) * 32 + q * 4]);
            a0 = fmaf(hA.x, b0[q*4+0], a0); a1 = fmaf(hA.x, b1[q*4+0], a1);
            a2 = fmaf(hB.x, b0[q*4+0], a2); a3 = fmaf(hB.x, b1[q*4+0], a3);
            a0 = fmaf(hA.y, b0[q*4+1], a0); a1 = fmaf(hA.y, b1[q*4+1], a1);
            a2 = fmaf(hB.y, b0[q*4+1], a2); a3 = fmaf(hB.y, b1[q*4+1], a3);
            a0 = fmaf(hA.z, b0[q*4+2], a0); a1 = fmaf(hA.z, b1[q*4+2], a1);
            a2 = fmaf(hB.z, b0[q*4+2], a2); a3 = fmaf(hB.z, b1[q*4+2], a3);
            a0 = fmaf(hA.w, b0[q*4+3], a0); a1 = fmaf(hA.w, b1[q*4+3], a1);
            a2 = fmaf(hB.w, b0[q*4+3], a2); a3 = fmaf(hB.w, b1[q*4+3], a3);
        }
        *reinterpret_cast<__nv_bfloat162*>(&g_G[(size_t)(n0 + nn) * 4096 + c0]) =
            __floats2bfloat162_rn(a0, a1);
        *reinterpret_cast<__nv_bfloat162*>(&g_G[(size_t)(n0 + nn + 1) * 4096 + c0]) =
            __floats2bfloat162_rn(a2, a3);
    }
    for (; nn < nmax; nn++) {
        float a0 = 0.f, a1 = 0.f;
#pragma unroll
        for (int q = 0; q < 8; q++) {
            float4 hA = *reinterpret_cast<const float4*>(&hs[nn * 32 + q * 4]);
            a0 = fmaf(hA.x, b0[q*4+0], a0); a1 = fmaf(hA.x, b1[q*4+0], a1);
            a0 = fmaf(hA.y, b0[q*4+1], a0); a1 = fmaf(hA.y, b1[q*4+1], a1);
            a0 = fmaf(hA.z, b0[q*4+2], a0); a1 = fmaf(hA.z, b1[q*4+2], a1);
            a0 = fmaf(hA.w, b0[q*4+3], a0); a1 = fmaf(hA.w, b1[q*4+3], a1);
        }
        *reinterpret_cast<__nv_bfloat162*>(&g_G[(size_t)(n0 + nn) * 4096 + c0]) =
            __floats2bfloat162_rn(a0, a1);
    }
}

// ---------------- histograms ----------------
__global__ void hist_kernel(const int* __restrict__ ei, int E) {
    int e = blockIdx.x * blockDim.x + threadIdx.x;
    if (e >= E) return;
    atomicAdd(&g_deg[ei[E + e]], 1);
    atomicAdd(&g_cnt[ei[e]], 1);
}

// ---------------- exclusive scan of col-degrees ----------------
__global__ void scan_kernel(int N, int E) {
    __shared__ int s[1024];
    int tid = threadIdx.x;
    int base = tid * 10;
    int local[10];
    int sum = 0;
#pragma unroll
    for (int i = 0; i < 10; i++) {
        int idx = base + i;
        int v = (idx < N) ? g_deg[idx] : 0;
        local[i] = sum; sum += v;
    }
    s[tid] = sum;
    __syncthreads();
    for (int off = 1; off < 1024; off <<= 1) {
        int v = (tid >= off) ? s[tid - off] : 0;
        __syncthreads();
        s[tid] += v;
        __syncthreads();
    }
    int pre = (tid > 0) ? s[tid - 1] : 0;
#pragma unroll
    for (int i = 0; i < 10; i++) {
        int idx = base + i;
        if (idx < N) {
            int v = pre + local[i];
            g_cur[idx] = v;
            g_off[idx] = v;
        }
    }
    if (tid == 0) g_off[N] = E;
}

// ---------------- scatter: build fully sorted edge records ----------------
__global__ void scatter_kernel(const int* __restrict__ ei, const float* __restrict__ ea,
                               const float* __restrict__ coord, int E) {
    int e = blockIdx.x * blockDim.x + threadIdx.x;
    if (e >= E) return;
    int row = ei[e];
    int col = ei[E + e];
    int pos = atomicAdd(&g_cur[col], 1);
    g_srow[pos] = row;
    float a0 = ea[e * 6 + 0], a1 = ea[e * 6 + 1], a2 = ea[e * 6 + 2];
    float a3 = ea[e * 6 + 3], a4 = ea[e * 6 + 4], a5 = ea[e * 6 + 5];
    float4* sp = reinterpret_cast<float4*>(&g_sea[(size_t)pos * 8]);
    sp[0] = make_float4(a0, a1, a2, a3);
    sp[1] = make_float4(a4, a5, 0.f, 0.f);
    float c0 = coord[row * 3 + 0] - coord[col * 3 + 0];
    float c1 = coord[row * 3 + 1] - coord[col * 3 + 1];
    float c2 = coord[row * 3 + 2] - coord[col * 3 + 2];
    *reinterpret_cast<float4*>(&g_scd[(size_t)pos * 4]) = make_float4(c0, c1, c2, 0.f);
}

// ---------------- edge kernel: warp per node, G row in registers ----------------
__global__ __launch_bounds__(256) void edge_kernel(
        const float* __restrict__ Wk1, const float* __restrict__ bk1,
        const float* __restrict__ Wc1, const float* __restrict__ bc1,
        const float* __restrict__ Wc2, int N) {
    __shared__ float sWk1[768], sbk1[128], sbc1[64], sWc2[64];
    __shared__ float2 sWc1p[1024];
    __shared__ float s_rz[8][128];
    int tid = threadIdx.x;
    for (int t = tid; t < 768; t += 256)  sWk1[t] = Wk1[t];
    for (int t = tid; t < 1024; t += 256) {
        int o = t >> 5, l = t & 31;
        sWc1p[t] = make_float2(Wc1[o * 64 + l], Wc1[o * 64 + 32 + l]);
    }
    if (tid < 128) sbk1[tid] = bk1[tid];
    if (tid < 64)  sbc1[tid] = bc1[tid];
    if (tid < 64)  sWc2[tid] = Wc2[tid];
    __syncthreads();

    int warp = tid >> 5, lane = tid & 31;
    const unsigned FULL = 0xffffffffu;
    int gw = blockIdx.x * 8 + warp;
    int nwarps = gridDim.x * 8;

    for (int n = gw; n < N; n += nwarps) {
        int j0 = g_off[n], j1 = g_off[n + 1];
        if (j0 == j1) continue;

        // G[n] into registers: lane owns o=lane; chunk kc at uint4 index kc*32+lane
        const uint4* gp = reinterpret_cast<const uint4*>(g_G + (size_t)n * 4096);
        uint4 gv[16];
#pragma unroll
        for (int kc = 0; kc < 16; kc++) gv[kc] = gp[kc * 32 + lane];
        float hbv = g_hb[n * 32 + lane];

        for (int j = j0; j < j1; j++) {
            int row = g_srow[j];

            float eav = (lane < 6) ? g_sea[(size_t)j * 8 + lane] : 0.f;
            float a0 = __shfl_sync(FULL, eav, 0), a1 = __shfl_sync(FULL, eav, 1);
            float a2 = __shfl_sync(FULL, eav, 2), a3 = __shfl_sync(FULL, eav, 3);
            float a4 = __shfl_sync(FULL, eav, 4), a5 = __shfl_sync(FULL, eav, 5);

            // rz = relu(ea @ Wk1 + bk1)
#pragma unroll
            for (int r = 0; r < 4; r++) {
                int k = r * 32 + lane;
                float v = sbk1[k];
                v = fmaf(a0, sWk1[k], v);
                v = fmaf(a1, sWk1[128 + k], v);
                v = fmaf(a2, sWk1[256 + k], v);
                v = fmaf(a3, sWk1[384 + k], v);
                v = fmaf(a4, sWk1[512 + k], v);
                v = fmaf(a5, sWk1[640 + k], v);
                s_rz[warp][k] = fmaxf(v, 0.f);
            }
            __syncwarp();

            // ef = hb + rz . G  (two independent accumulator chains)
            float accA = hbv, accB = 0.f;
#pragma unroll
            for (int kc = 0; kc < 8; kc++) {
                float4 ra = *reinterpret_cast<const float4*>(&s_rz[warp][kc * 8]);
                float4 rb = *reinterpret_cast<const float4*>(&s_rz[warp][kc * 8 + 4]);
                float4 rc = *reinterpret_cast<const float4*>(&s_rz[warp][(kc + 8) * 8]);
                float4 rd = *reinterpret_cast<const float4*>(&s_rz[warp][(kc + 8) * 8 + 4]);
                uint4 gA = gv[kc];
                uint4 gB = gv[kc + 8];
                float2 f;
                f = __bfloat1622float2(*reinterpret_cast<const __nv_bfloat162*>(&gA.x));
                accA = fmaf(ra.x, f.x, accA); accA = fmaf(ra.y, f.y, accA);
                f = __bfloat1622float2(*reinterpret_cast<const __nv_bfloat162*>(&gA.y));
                accA = fmaf(ra.z, f.x, accA); accA = fmaf(ra.w, f.y, accA);
                f = __bfloat1622float2(*reinterpret_cast<const __nv_bfloat162*>(&gA.z));
                accA = fmaf(rb.x, f.x, accA); accA = fmaf(rb.y, f.y, accA);
                f = __bfloat1622float2(*reinterpret_cast<const __nv_bfloat162*>(&gA.w));
                accA = fmaf(rb.z, f.x, accA); accA = fmaf(rb.w, f.y, accA);
                f = __bfloat1622float2(*reinterpret_cast<const __nv_bfloat162*>(&gB.x));
                accB = fmaf(rc.x, f.x, accB); accB = fmaf(rc.y, f.y, accB);
                f = __bfloat1622float2(*reinterpret_cast<const __nv_bfloat162*>(&gB.y));
                accB = fmaf(rc.z, f.x, accB); accB = fmaf(rc.w, f.y, accB);
                f = __bfloat1622float2(*reinterpret_cast<const __nv_bfloat162*>(&gB.z));
                accB = fmaf(rd.x, f.x, accB); accB = fmaf(rd.y, f.y, accB);
                f = __bfloat1622float2(*reinterpret_cast<const __nv_bfloat162*>(&gB.w));
                accB = fmaf(rd.z, f.x, accB); accB = fmaf(rd.w, f.y, accB);
            }
            float acc = accA + accB;
            __syncwarp();   // s_rz reads done before next edge overwrites

            // coord MLP: w_c = relu(ef @ Wc1 + bc1) @ Wc2
            float t0 = sbc1[lane], t1 = sbc1[32 + lane];
#pragma unroll
            for (int o = 0; o < 32; o++) {
                float2 w = sWc1p[o * 32 + lane];
                float eo = __shfl_sync(FULL, acc, o);
                t0 = fmaf(eo, w.x, t0); t1 = fmaf(eo, w.y, t1);
            }
            t0 = fmaxf(t0, 0.f); t1 = fmaxf(t1, 0.f);
            float p = fmaf(t0, sWc2[lane], t1 * sWc2[32 + lane]);
#pragma unroll
            for (int off = 16; off; off >>= 1)
                p += __shfl_xor_sync(FULL, p, off);

            atomicAdd(&g_sum_ef[row * 32 + lane], acc);
            if (lane < 3) {
                float cd = g_scd[(size_t)j * 4 + lane];
                atomicAdd(&g_sum_tr[row * 3 + lane], cd * p);
            }
        }
    }
}

// ---------------- node epilogue ----------------
__global__ void node_kernel(const float* __restrict__ h, const float* __restrict__ coord,
                            const float* __restrict__ root, const float* __restrict__ bias,
                            float* __restrict__ out, int N) {
    int warp = threadIdx.x >> 5, lane = threadIdx.x & 31;
    int n = blockIdx.x * 8 + warp;
    if (n >= N) return;
    float hv = h[n * 32 + lane];
    float inv = 1.f / fmaxf((float)g_cnt[n], 1.f);
    float agg = g_sum_ef[n * 32 + lane] * inv + bias[lane];
#pragma unroll
    for (int i = 0; i < 32; i++)
        agg = fmaf(__shfl_sync(0xffffffffu, hv, i), root[i * 32 + lane], agg);
    out[n * 32 + lane] = hv + fmaxf(agg, 0.f) * 0.25f;
    if (lane < 3)
        out[N * 32 + n * 3 + lane] = g_sum_tr[n * 3 + lane] * inv * 0.25f + coord[n * 3 + lane];
}

extern "C" void kernel_launch(void* const* d_in, const int* in_sizes, int n_in,
                              void* d_out, int out_size) {
    const float* h     = (const float*)d_in[0];
    const int*   ei    = (const int*)  d_in[1];
    const float* coord = (const float*)d_in[2];
    const float* ea    = (const float*)d_in[3];
    const float* Wk1   = (const float*)d_in[4];
    const float* bk1   = (const float*)d_in[5];
    const float* Wk2   = (const float*)d_in[6];
    const float* bk2   = (const float*)d_in[7];
    const float* root  = (const float*)d_in[8];
    const float* bias  = (const float*)d_in[9];
    const float* Wc1   = (const float*)d_in[10];
    const float* bc1   = (const float*)d_in[11];
    const float* Wc2   = (const float*)d_in[12];

    int N = in_sizes[0] / 32;
    int E = in_sizes[1] / 2;
    float* out = (float*)d_out;

    zero_kernel<<<(N * 32 + 255) / 256, 256>>>(N);
    bperm_kernel<<<(4096 * 32 + 255) / 256, 256>>>(Wk2);
    hb_kernel<<<(N + 7) / 8, 256>>>(h, bk2, N);
    dim3 gg((N + 63) / 64, 8);
    g_kernel<<<gg, 256>>>(h, N);
    hist_kernel<<<(E + 255) / 256, 256>>>(ei, E);
    scan_kernel<<<1, 1024>>>(N, E);
    scatter_kernel<<<(E + 255) / 256, 256>>>(ei, ea, coord, E);
    edge_kernel<<<296, 256>>>(Wk1, bk1, Wc1, bc1, Wc2, N);
    node_kernel<<<(N + 7) / 8, 256>>>(h, coord, root, bias, out, N);
}

// round 7
// speedup vs baseline: 1.1495x; 1.1495x over previous
#include <cuda_runtime.h>
#include <cuda_bf16.h>
#include <cstdint>

#define NN 10240
#define EE 160000

// Scratch (static device globals)
__device__ __nv_bfloat16 g_G[(size_t)NN * 4096];   // G[n][kb][o][ki]: kb=k/8 (16), o (32), ki=k%8 (8)
__device__ float g_hb[NN * 32];
__device__ float g_Bperm[4096 * 32];
__device__ float g_sum_ef[NN * 32];
__device__ float g_sum_tr[NN * 3];
__device__ int   g_cnt[NN];        // row-degree (mean)
__device__ int   g_deg[NN];        // col-degree (sort)
__device__ int   g_cur[NN];
// sorted edge data (by col)
__device__ int   g_srow[EE];
__device__ int   g_scol[EE];
__device__ float g_sea[(size_t)EE * 8];
__device__ float g_scd[(size_t)EE * 4];

// ---------------- f32x2 helpers ----------------
__device__ __forceinline__ unsigned long long pk2(float x, float y) {
    unsigned long long r;
    asm("mov.b64 %0, {%1, %2};" : "=l"(r) : "f"(x), "f"(y));
    return r;
}
__device__ __forceinline__ void ffma2(unsigned long long& d,
                                      unsigned long long a, unsigned long long b) {
    asm("fma.rn.f32x2 %0, %1, %2, %3;" : "=l"(d) : "l"(a), "l"(b), "l"(d));
}
__device__ __forceinline__ float2 upk2(unsigned long long v) {
    float x, y;
    asm("mov.b64 {%0, %1}, %2;" : "=f"(x), "=f"(y) : "l"(v));
    return make_float2(x, y);
}

// ---------------- zero ----------------
__global__ void zero_kernel(int N) {
    int i = blockIdx.x * blockDim.x + threadIdx.x;
    if (i < N * 32) g_sum_ef[i] = 0.f;
    if (i < N * 3)  g_sum_tr[i] = 0.f;
    if (i < N) { g_cnt[i] = 0; g_deg[i] = 0; }
}

// ---------------- permute Wk2 for the [kb][o][ki] G layout ----------------
__global__ void bperm_kernel(const float* __restrict__ Wk2) {
    int idx = blockIdx.x * blockDim.x + threadIdx.x;
    if (idx >= 4096 * 32) return;
    int i = idx & 31;
    int c = idx >> 5;
    int kb = c >> 8;
    int o  = (c >> 3) & 31;
    int ki = c & 7;
    int k  = kb * 8 + ki;
    g_Bperm[idx] = Wk2[k * 1024 + i * 32 + o];
}

// ---------------- hb = h @ bk2 ----------------
__global__ void hb_kernel(const float* __restrict__ h, const float* __restrict__ bk2, int N) {
    int warp = threadIdx.x >> 5, lane = threadIdx.x & 31;
    int n = blockIdx.x * 8 + warp;
    if (n >= N) return;
    float hv = h[n * 32 + lane];
    float acc = 0.f;
#pragma unroll
    for (int i = 0; i < 32; i++)
        acc = fmaf(__shfl_sync(0xffffffffu, hv, i), bk2[i * 32 + lane], acc);
    g_hb[n * 32 + lane] = acc;
}

// ---------------- G = H @ Bperm, bf16, f32x2: 2 cols packed per thread ----------------
__global__ __launch_bounds__(256) void g_kernel(const float* __restrict__ h, int N) {
    __shared__ __align__(16) float2 hs[64 * 32];   // duplicated (h,h), 16KB
    int n0 = blockIdx.x * 64;
    int c0 = (blockIdx.y * 256 + threadIdx.x) * 2;
    int lim = N * 32;
    for (int t = threadIdx.x; t < 64 * 32; t += 256) {
        int gi = n0 * 32 + t;
        float v = (gi < lim) ? h[gi] : 0.f;
        hs[t] = make_float2(v, v);
    }
    __syncthreads();
    unsigned long long bp[32];
#pragma unroll
    for (int q = 0; q < 8; q++) {
        float4 v0 = *reinterpret_cast<const float4*>(&g_Bperm[(size_t)c0 * 32 + q * 4]);
        float4 v1 = *reinterpret_cast<const float4*>(&g_Bperm[(size_t)(c0 + 1) * 32 + q * 4]);
        bp[q*4+0] = pk2(v0.x, v1.x);
        bp[q*4+1] = pk2(v0.y, v1.y);
        bp[q*4+2] = pk2(v0.z, v1.z);
        bp[q*4+3] = pk2(v0.w, v1.w);
    }
    int nmax = min(64, N - n0);
    for (int nn = 0; nn < nmax; nn++) {
        const ulonglong2* hp = reinterpret_cast<const ulonglong2*>(&hs[nn * 32]);
        unsigned long long acc0 = 0ull, acc1 = 0ull;  // (0.f, 0.f)
#pragma unroll
        for (int i = 0; i < 8; i++) {
            ulonglong2 hA = hp[2 * i];
            ulonglong2 hB = hp[2 * i + 1];
            ffma2(acc0, hA.x, bp[4*i+0]);
            ffma2(acc1, hA.y, bp[4*i+1]);
            ffma2(acc0, hB.x, bp[4*i+2]);
            ffma2(acc1, hB.y, bp[4*i+3]);
        }
        float2 r0 = upk2(acc0), r1 = upk2(acc1);
        *reinterpret_cast<__nv_bfloat162*>(&g_G[(size_t)(n0 + nn) * 4096 + c0]) =
            __floats2bfloat162_rn(r0.x + r1.x, r0.y + r1.y);
    }
}

// ---------------- histograms ----------------
__global__ void hist_kernel(const int* __restrict__ ei, int E) {
    int e = blockIdx.x * blockDim.x + threadIdx.x;
    if (e >= E) return;
    atomicAdd(&g_deg[ei[E + e]], 1);
    atomicAdd(&g_cnt[ei[e]], 1);
}

// ---------------- exclusive scan of col-degrees ----------------
__global__ void scan_kernel(int N) {
    __shared__ int s[1024];
    int tid = threadIdx.x;
    int base = tid * 10;
    int local[10];
    int sum = 0;
#pragma unroll
    for (int i = 0; i < 10; i++) {
        int idx = base + i;
        int v = (idx < N) ? g_deg[idx] : 0;
        local[i] = sum; sum += v;
    }
    s[tid] = sum;
    __syncthreads();
    for (int off = 1; off < 1024; off <<= 1) {
        int v = (tid >= off) ? s[tid - off] : 0;
        __syncthreads();
        s[tid] += v;
        __syncthreads();
    }
    int pre = (tid > 0) ? s[tid - 1] : 0;
#pragma unroll
    for (int i = 0; i < 10; i++) {
        int idx = base + i;
        if (idx < N) g_cur[idx] = pre + local[i];
    }
}

// ---------------- scatter: build fully sorted edge records ----------------
__global__ void scatter_kernel(const int* __restrict__ ei, const float* __restrict__ ea,
                               const float* __restrict__ coord, int E) {
    int e = blockIdx.x * blockDim.x + threadIdx.x;
    if (e >= E) return;
    int row = ei[e];
    int col = ei[E + e];
    int pos = atomicAdd(&g_cur[col], 1);
    g_srow[pos] = row;
    g_scol[pos] = col;
    float a0 = ea[e * 6 + 0], a1 = ea[e * 6 + 1], a2 = ea[e * 6 + 2];
    float a3 = ea[e * 6 + 3], a4 = ea[e * 6 + 4], a5 = ea[e * 6 + 5];
    float4* sp = reinterpret_cast<float4*>(&g_sea[(size_t)pos * 8]);
    sp[0] = make_float4(a0, a1, a2, a3);
    sp[1] = make_float4(a4, a5, 0.f, 0.f);
    float c0 = coord[row * 3 + 0] - coord[col * 3 + 0];
    float c1 = coord[row * 3 + 1] - coord[col * 3 + 1];
    float c2 = coord[row * 3 + 2] - coord[col * 3 + 2];
    *reinterpret_cast<float4*>(&g_scd[(size_t)pos * 4]) = make_float4(c0, c1, c2, 0.f);
}

// ---------------- edge kernel: 2 edges/warp-iter, sorted, coalesced gather ----------------
__global__ __launch_bounds__(256) void edge_kernel(
        const float* __restrict__ Wk1, const float* __restrict__ bk1,
        const float* __restrict__ Wc1, const float* __restrict__ bc1,
        const float* __restrict__ Wc2, int E) {
    __shared__ float sWk1[768], sbk1[128], sbc1[64], sWc2[64];
    __shared__ float2 sWc1p[1024];          // (o,lane) -> (Wc1[o*64+lane], Wc1[o*64+32+lane])
    __shared__ float s_rz[8][2][128];
    int tid = threadIdx.x;
    for (int t = tid; t < 768; t += 256)  sWk1[t] = Wk1[t];
    for (int t = tid; t < 1024; t += 256) {
        int o = t >> 5, l = t & 31;
        sWc1p[t] = make_float2(Wc1[o * 64 + l], Wc1[o * 64 + 32 + l]);
    }
    if (tid < 128) sbk1[tid] = bk1[tid];
    if (tid < 64)  sbc1[tid] = bc1[tid];
    if (tid < 64)  sWc2[tid] = Wc2[tid];
    __syncthreads();

    int warp = tid >> 5, lane = tid & 31;
    const unsigned FULL = 0xffffffffu;
    int per = (E + gridDim.x - 1) / gridDim.x;
    int j0 = blockIdx.x * per;
    int j1 = min(j0 + per, E);

    for (int j = j0 + warp * 2; j < j1; j += 16) {
        int jA = j;
        int jB = j + 1;
        bool vB = jB < j1;
        int row0 = g_srow[jA], col0 = g_scol[jA];
        int row1 = vB ? g_srow[jB] : row0;
        int col1 = vB ? g_scol[jB] : col0;

        float eaA = (lane < 6) ? g_sea[(size_t)jA * 8 + lane] : 0.f;
        float eaB = (vB && lane < 6) ? g_sea[(size_t)jB * 8 + lane] : 0.f;
        float a0A = __shfl_sync(FULL, eaA, 0), a1A = __shfl_sync(FULL, eaA, 1);
        float a2A = __shfl_sync(FULL, eaA, 2), a3A = __shfl_sync(FULL, eaA, 3);
        float a4A = __shfl_sync(FULL, eaA, 4), a5A = __shfl_sync(FULL, eaA, 5);
        float a0B = __shfl_sync(FULL, eaB, 0), a1B = __shfl_sync(FULL, eaB, 1);
        float a2B = __shfl_sync(FULL, eaB, 2), a3B = __shfl_sync(FULL, eaB, 3);
        float a4B = __shfl_sync(FULL, eaB, 4), a5B = __shfl_sync(FULL, eaB, 5);

        // rz = relu(ea @ Wk1 + bk1) for both edges; weight LDS shared
#pragma unroll
        for (int r = 0; r < 4; r++) {
            int k = r * 32 + lane;
            float w0 = sWk1[k], w1 = sWk1[128 + k], w2 = sWk1[256 + k];
            float w3 = sWk1[384 + k], w4 = sWk1[512 + k], w5 = sWk1[640 + k];
            float b = sbk1[k];
            float vA = b, vBv = b;
            vA = fmaf(a0A, w0, vA); vBv = fmaf(a0B, w0, vBv);
            vA = fmaf(a1A, w1, vA); vBv = fmaf(a1B, w1, vBv);
            vA = fmaf(a2A, w2, vA); vBv = fmaf(a2B, w2, vBv);
            vA = fmaf(a3A, w3, vA); vBv = fmaf(a3B, w3, vBv);
            vA = fmaf(a4A, w4, vA); vBv = fmaf(a4B, w4, vBv);
            vA = fmaf(a5A, w5, vA); vBv = fmaf(a5B, w5, vBv);
            s_rz[warp][0][k] = fmaxf(vA, 0.f);
            s_rz[warp][1][k] = fmaxf(vBv, 0.f);
        }
        __syncwarp();

        // ef = hb[col] + rz . G[col]: lane owns output o=lane.
        const __nv_bfloat16* gp0 = g_G + (size_t)col0 * 4096 + lane * 8;
        const __nv_bfloat16* gp1 = g_G + (size_t)col1 * 4096 + lane * 8;
        float acc0 = g_hb[col0 * 32 + lane];
        float acc1 = g_hb[col1 * 32 + lane];
#pragma unroll
        for (int kc = 0; kc < 16; kc++) {
            uint4 gv0 = *reinterpret_cast<const uint4*>(gp0 + kc * 256);
            uint4 gv1 = *reinterpret_cast<const uint4*>(gp1 + kc * 256);
            float4 ra0 = *reinterpret_cast<const float4*>(&s_rz[warp][0][kc * 8]);
            float4 rb0 = *reinterpret_cast<const float4*>(&s_rz[warp][0][kc * 8 + 4]);
            float4 ra1 = *reinterpret_cast<const float4*>(&s_rz[warp][1][kc * 8]);
            float4 rb1 = *reinterpret_cast<const float4*>(&s_rz[warp][1][kc * 8 + 4]);
            float2 f;
            f = __bfloat1622float2(*reinterpret_cast<const __nv_bfloat162*>(&gv0.x));
            acc0 = fmaf(ra0.x, f.x, acc0); acc0 = fmaf(ra0.y, f.y, acc0);
            f = __bfloat1622float2(*reinterpret_cast<const __nv_bfloat162*>(&gv0.y));
            acc0 = fmaf(ra0.z, f.x, acc0); acc0 = fmaf(ra0.w, f.y, acc0);
            f = __bfloat1622float2(*reinterpret_cast<const __nv_bfloat162*>(&gv0.z));
            acc0 = fmaf(rb0.x, f.x, acc0); acc0 = fmaf(rb0.y, f.y, acc0);
            f = __bfloat1622float2(*reinterpret_cast<const __nv_bfloat162*>(&gv0.w));
            acc0 = fmaf(rb0.z, f.x, acc0); acc0 = fmaf(rb0.w, f.y, acc0);
            f = __bfloat1622float2(*reinterpret_cast<const __nv_bfloat162*>(&gv1.x));
            acc1 = fmaf(ra1.x, f.x, acc1); acc1 = fmaf(ra1.y, f.y, acc1);
            f = __bfloat1622float2(*reinterpret_cast<const __nv_bfloat162*>(&gv1.y));
            acc1 = fmaf(ra1.z, f.x, acc1); acc1 = fmaf(ra1.w, f.y, acc1);
            f = __bfloat1622float2(*reinterpret_cast<const __nv_bfloat162*>(&gv1.z));
            acc1 = fmaf(rb1.x, f.x, acc1); acc1 = fmaf(rb1.y, f.y, acc1);
            f = __bfloat1622float2(*reinterpret_cast<const __nv_bfloat162*>(&gv1.w));
            acc1 = fmaf(rb1.z, f.x, acc1); acc1 = fmaf(rb1.w, f.y, acc1);
        }

        // coord MLP for both edges, ef broadcast via shuffle
        float t0A = sbc1[lane], t1A = sbc1[32 + lane];
        float t0B = t0A, t1B = t1A;
#pragma unroll
        for (int o = 0; o < 32; o++) {
            float2 w = sWc1p[o * 32 + lane];
            float eA = __shfl_sync(FULL, acc0, o);
            float eB = __shfl_sync(FULL, acc1, o);
            t0A = fmaf(eA, w.x, t0A); t1A = fmaf(eA, w.y, t1A);
            t0B = fmaf(eB, w.x, t0B); t1B = fmaf(eB, w.y, t1B);
        }
        t0A = fmaxf(t0A, 0.f); t1A = fmaxf(t1A, 0.f);
        t0B = fmaxf(t0B, 0.f); t1B = fmaxf(t1B, 0.f);
        float wc2a = sWc2[lane], wc2b = sWc2[32 + lane];
        float pA = fmaf(t0A, wc2a, t1A * wc2b);
        float pB = fmaf(t0B, wc2a, t1B * wc2b);
#pragma unroll
        for (int off = 16; off; off >>= 1) {
            pA += __shfl_xor_sync(FULL, pA, off);
            pB += __shfl_xor_sync(FULL, pB, off);
        }

        atomicAdd(&g_sum_ef[row0 * 32 + lane], acc0);
        if (vB) atomicAdd(&g_sum_ef[row1 * 32 + lane], acc1);
        if (lane < 3) {
            float cdA = g_scd[(size_t)jA * 4 + lane];
            atomicAdd(&g_sum_tr[row0 * 3 + lane], cdA * pA);
            if (vB) {
                float cdB = g_scd[(size_t)jB * 4 + lane];
                atomicAdd(&g_sum_tr[row1 * 3 + lane], cdB * pB);
            }
        }
        __syncwarp();
    }
}

// ---------------- node epilogue ----------------
__global__ void node_kernel(const float* __restrict__ h, const float* __restrict__ coord,
                            const float* __restrict__ root, const float* __restrict__ bias,
                            float* __restrict__ out, int N) {
    int warp = threadIdx.x >> 5, lane = threadIdx.x & 31;
    int n = blockIdx.x * 8 + warp;
    if (n >= N) return;
    float hv = h[n * 32 + lane];
    float inv = 1.f / fmaxf((float)g_cnt[n], 1.f);
    float agg = g_sum_ef[n * 32 + lane] * inv + bias[lane];
#pragma unroll
    for (int i = 0; i < 32; i++)
        agg = fmaf(__shfl_sync(0xffffffffu, hv, i), root[i * 32 + lane], agg);
    out[n * 32 + lane] = hv + fmaxf(agg, 0.f) * 0.25f;
    if (lane < 3)
        out[N * 32 + n * 3 + lane] = g_sum_tr[n * 3 + lane] * inv * 0.25f + coord[n * 3 + lane];
}

extern "C" void kernel_launch(void* const* d_in, const int* in_sizes, int n_in,
                              void* d_out, int out_size) {
    const float* h     = (const float*)d_in[0];
    const int*   ei    = (const int*)  d_in[1];
    const float* coord = (const float*)d_in[2];
    const float* ea    = (const float*)d_in[3];
    const float* Wk1   = (const float*)d_in[4];
    const float* bk1   = (const float*)d_in[5];
    const float* Wk2   = (const float*)d_in[6];
    const float* bk2   = (const float*)d_in[7];
    const float* root  = (const float*)d_in[8];
    const float* bias  = (const float*)d_in[9];
    const float* Wc1   = (const float*)d_in[10];
    const float* bc1   = (const float*)d_in[11];
    const float* Wc2   = (const float*)d_in[12];

    int N = in_sizes[0] / 32;
    int E = in_sizes[1] / 2;
    float* out = (float*)d_out;

    zero_kernel<<<(N * 32 + 255) / 256, 256>>>(N);
    bperm_kernel<<<(4096 * 32 + 255) / 256, 256>>>(Wk2);
    hb_kernel<<<(N + 7) / 8, 256>>>(h, bk2, N);
    dim3 gg((N + 63) / 64, 8);
    g_kernel<<<gg, 256>>>(h, N);
    hist_kernel<<<(E + 255) / 256, 256>>>(ei, E);
    scan_kernel<<<1, 1024>>>(N);
    scatter_kernel<<<(E + 255) / 256, 256>>>(ei, ea, coord, E);
    edge_kernel<<<592, 256>>>(Wk1, bk1, Wc1, bc1, Wc2, E);
    node_kernel<<<(N + 7) / 8, 256>>>(h, coord, root, bias, out, N);
}

// round 9
// speedup vs baseline: 1.3112x; 1.1407x over previous
#include <cuda_runtime.h>
#include <cuda_bf16.h>
#include <cstdint>

#define NN 10240
#define EE 160000

// Scratch (static device globals)
__device__ __nv_bfloat16 g_G[(size_t)NN * 4096];   // G[n][kb][o][ki]: kb=k/8 (16), o (32), ki=k%8 (8)
__device__ float g_hb[NN * 32];
__device__ float g_Bperm[4096 * 32];
__device__ float g_sum_ef[NN * 32];
__device__ float g_sum_tr[NN * 3];
__device__ int   g_cnt[NN];        // row-degree (mean)
__device__ int   g_deg[NN];        // col-degree (sort)
__device__ int   g_cur[NN];
// sorted edge data (by col)
__device__ int   g_srow[EE];
__device__ int   g_scol[EE];
__device__ float g_sea[(size_t)EE * 8];
__device__ float g_scd[(size_t)EE * 4];

// ---------------- zero ----------------
__global__ void zero_kernel(int N) {
    int i = blockIdx.x * blockDim.x + threadIdx.x;
    if (i < N * 32) g_sum_ef[i] = 0.f;
    if (i < N * 3)  g_sum_tr[i] = 0.f;
    if (i < N) { g_cnt[i] = 0; g_deg[i] = 0; }
}

// ---------------- permute Wk2 for the [kb][o][ki] G layout ----------------
__global__ void bperm_kernel(const float* __restrict__ Wk2) {
    int idx = blockIdx.x * blockDim.x + threadIdx.x;
    if (idx >= 4096 * 32) return;
    int i = idx & 31;
    int c = idx >> 5;
    int kb = c >> 8;
    int o  = (c >> 3) & 31;
    int ki = c & 7;
    int k  = kb * 8 + ki;
    g_Bperm[idx] = Wk2[k * 1024 + i * 32 + o];
}

// ---------------- hb = h @ bk2 ----------------
__global__ void hb_kernel(const float* __restrict__ h, const float* __restrict__ bk2, int N) {
    int warp = threadIdx.x >> 5, lane = threadIdx.x & 31;
    int n = blockIdx.x * 8 + warp;
    if (n >= N) return;
    float hv = h[n * 32 + lane];
    float acc = 0.f;
#pragma unroll
    for (int i = 0; i < 32; i++)
        acc = fmaf(__shfl_sync(0xffffffffu, hv, i), bk2[i * 32 + lane], acc);
    g_hb[n * 32 + lane] = acc;
}

// ---------------- G = H @ Bperm, bf16, 2 cols/thread (R5 proven version) ----------------
__global__ __launch_bounds__(256) void g_kernel(const float* __restrict__ h, int N) {
    __shared__ float hs[64 * 32];
    int n0 = blockIdx.x * 64;
    int c0 = (blockIdx.y * 256 + threadIdx.x) * 2;
    int lim = N * 32;
    for (int t = threadIdx.x; t < 64 * 32; t += 256) {
        int gi = n0 * 32 + t;
        hs[t] = (gi < lim) ? h[gi] : 0.f;
    }
    __syncthreads();
    float b0[32], b1[32];
#pragma unroll
    for (int q = 0; q < 8; q++) {
        float4 v0 = *reinterpret_cast<const float4*>(&g_Bperm[(size_t)c0 * 32 + q * 4]);
        float4 v1 = *reinterpret_cast<const float4*>(&g_Bperm[(size_t)(c0 + 1) * 32 + q * 4]);
        b0[q*4+0] = v0.x; b0[q*4+1] = v0.y; b0[q*4+2] = v0.z; b0[q*4+3] = v0.w;
        b1[q*4+0] = v1.x; b1[q*4+1] = v1.y; b1[q*4+2] = v1.z; b1[q*4+3] = v1.w;
    }
    int nmax = min(64, N - n0);
    for (int nn = 0; nn < nmax; nn++) {
        float a0 = 0.f, a1 = 0.f;
#pragma unroll
        for (int q = 0; q < 8; q++) {
            float4 hv = *reinterpret_cast<const float4*>(&hs[nn * 32 + q * 4]);
            a0 = fmaf(hv.x, b0[q*4+0], a0); a1 = fmaf(hv.x, b1[q*4+0], a1);
            a0 = fmaf(hv.y, b0[q*4+1], a0); a1 = fmaf(hv.y, b1[q*4+1], a1);
            a0 = fmaf(hv.z, b0[q*4+2], a0); a1 = fmaf(hv.z, b1[q*4+2], a1);
            a0 = fmaf(hv.w, b0[q*4+3], a0); a1 = fmaf(hv.w, b1[q*4+3], a1);
        }
        *reinterpret_cast<__nv_bfloat162*>(&g_G[(size_t)(n0 + nn) * 4096 + c0]) =
            __floats2bfloat162_rn(a0, a1);
    }
}

// ---------------- histograms ----------------
__global__ void hist_kernel(const int* __restrict__ ei, int E) {
    int e = blockIdx.x * blockDim.x + threadIdx.x;
    if (e >= E) return;
    atomicAdd(&g_deg[ei[E + e]], 1);
    atomicAdd(&g_cnt[ei[e]], 1);
}

// ---------------- exclusive scan of col-degrees ----------------
__global__ void scan_kernel(int N) {
    __shared__ int s[1024];
    int tid = threadIdx.x;
    int base = tid * 10;
    int local[10];
    int sum = 0;
#pragma unroll
    for (int i = 0; i < 10; i++) {
        int idx = base + i;
        int v = (idx < N) ? g_deg[idx] : 0;
        local[i] = sum; sum += v;
    }
    s[tid] = sum;
    __syncthreads();
    for (int off = 1; off < 1024; off <<= 1) {
        int v = (tid >= off) ? s[tid - off] : 0;
        __syncthreads();
        s[tid] += v;
        __syncthreads();
    }
    int pre = (tid > 0) ? s[tid - 1] : 0;
#pragma unroll
    for (int i = 0; i < 10; i++) {
        int idx = base + i;
        if (idx < N) g_cur[idx] = pre + local[i];
    }
}

// ---------------- scatter: build fully sorted edge records ----------------
__global__ void scatter_kernel(const int* __restrict__ ei, const float* __restrict__ ea,
                               const float* __restrict__ coord, int E) {
    int e = blockIdx.x * blockDim.x + threadIdx.x;
    if (e >= E) return;
    int row = ei[e];
    int col = ei[E + e];
    int pos = atomicAdd(&g_cur[col], 1);
    g_srow[pos] = row;
    g_scol[pos] = col;
    float a0 = ea[e * 6 + 0], a1 = ea[e * 6 + 1], a2 = ea[e * 6 + 2];
    float a3 = ea[e * 6 + 3], a4 = ea[e * 6 + 4], a5 = ea[e * 6 + 5];
    float4* sp = reinterpret_cast<float4*>(&g_sea[(size_t)pos * 8]);
    sp[0] = make_float4(a0, a1, a2, a3);
    sp[1] = make_float4(a4, a5, 0.f, 0.f);
    float c0 = coord[row * 3 + 0] - coord[col * 3 + 0];
    float c1 = coord[row * 3 + 1] - coord[col * 3 + 1];
    float c2 = coord[row * 3 + 2] - coord[col * 3 + 2];
    *reinterpret_cast<float4*>(&g_scd[(size_t)pos * 4]) = make_float4(c0, c1, c2, 0.f);
}

// ---------------- edge kernel: 2 edges/warp-iter, smem ef broadcast ----------------
__global__ __launch_bounds__(256) void edge_kernel(
        const float* __restrict__ Wk1, const float* __restrict__ bk1,
        const float* __restrict__ Wc1, const float* __restrict__ bc1,
        const float* __restrict__ Wc2, int E) {
    __shared__ float sWk1[768], sbk1[128], sbc1[64], sWc2[64];
    __shared__ float2 sWc1p[1024];          // (o,lane) -> (Wc1[o*64+lane], Wc1[o*64+32+lane])
    __shared__ float s_rz[8][2][128];
    __shared__ __align__(16) float s_ef[8][2][32];
    int tid = threadIdx.x;
    for (int t = tid; t < 768; t += 256)  sWk1[t] = Wk1[t];
    for (int t = tid; t < 1024; t += 256) {
        int o = t >> 5, l = t & 31;
        sWc1p[t] = make_float2(Wc1[o * 64 + l], Wc1[o * 64 + 32 + l]);
    }
    if (tid < 128) sbk1[tid] = bk1[tid];
    if (tid < 64)  sbc1[tid] = bc1[tid];
    if (tid < 64)  sWc2[tid] = Wc2[tid];
    __syncthreads();

    int warp = tid >> 5, lane = tid & 31;
    const unsigned FULL = 0xffffffffu;
    int per = (E + gridDim.x - 1) / gridDim.x;
    int j0 = blockIdx.x * per;
    int j1 = min(j0 + per, E);

    for (int j = j0 + warp * 2; j < j1; j += 16) {
        int jA = j;
        int jB = j + 1;
        bool vB = jB < j1;
        int row0 = g_srow[jA], col0 = g_scol[jA];
        int row1 = vB ? g_srow[jB] : row0;
        int col1 = vB ? g_scol[jB] : col0;

        float eaA = (lane < 6) ? g_sea[(size_t)jA * 8 + lane] : 0.f;
        float eaB = (vB && lane < 6) ? g_sea[(size_t)jB * 8 + lane] : 0.f;
        float a0A = __shfl_sync(FULL, eaA, 0), a1A = __shfl_sync(FULL, eaA, 1);
        float a2A = __shfl_sync(FULL, eaA, 2), a3A = __shfl_sync(FULL, eaA, 3);
        float a4A = __shfl_sync(FULL, eaA, 4), a5A = __shfl_sync(FULL, eaA, 5);
        float a0B = __shfl_sync(FULL, eaB, 0), a1B = __shfl_sync(FULL, eaB, 1);
        float a2B = __shfl_sync(FULL, eaB, 2), a3B = __shfl_sync(FULL, eaB, 3);
        float a4B = __shfl_sync(FULL, eaB, 4), a5B = __shfl_sync(FULL, eaB, 5);

        // rz = relu(ea @ Wk1 + bk1) for both edges; weight LDS shared
#pragma unroll
        for (int r = 0; r < 4; r++) {
            int k = r * 32 + lane;
            float w0 = sWk1[k], w1 = sWk1[128 + k], w2 = sWk1[256 + k];
            float w3 = sWk1[384 + k], w4 = sWk1[512 + k], w5 = sWk1[640 + k];
            float b = sbk1[k];
            float vA = b, vBv = b;
            vA = fmaf(a0A, w0, vA); vBv = fmaf(a0B, w0, vBv);
            vA = fmaf(a1A, w1, vA); vBv = fmaf(a1B, w1, vBv);
            vA = fmaf(a2A, w2, vA); vBv = fmaf(a2B, w2, vBv);
            vA = fmaf(a3A, w3, vA); vBv = fmaf(a3B, w3, vBv);
            vA = fmaf(a4A, w4, vA); vBv = fmaf(a4B, w4, vBv);
            vA = fmaf(a5A, w5, vA); vBv = fmaf(a5B, w5, vBv);
            s_rz[warp][0][k] = fmaxf(vA, 0.f);
            s_rz[warp][1][k] = fmaxf(vBv, 0.f);
        }
        __syncwarp();

        // ef = hb[col] + rz . G[col]: lane owns output o=lane.
        const __nv_bfloat16* gp0 = g_G + (size_t)col0 * 4096 + lane * 8;
        const __nv_bfloat16* gp1 = g_G + (size_t)col1 * 4096 + lane * 8;
        float acc0 = g_hb[col0 * 32 + lane];
        float acc1 = g_hb[col1 * 32 + lane];
#pragma unroll
        for (int kc = 0; kc < 16; kc++) {
            uint4 gv0 = *reinterpret_cast<const uint4*>(gp0 + kc * 256);
            uint4 gv1 = *reinterpret_cast<const uint4*>(gp1 + kc * 256);
            float4 ra0 = *reinterpret_cast<const float4*>(&s_rz[warp][0][kc * 8]);
            float4 rb0 = *reinterpret_cast<const float4*>(&s_rz[warp][0][kc * 8 + 4]);
            float4 ra1 = *reinterpret_cast<const float4*>(&s_rz[warp][1][kc * 8]);
            float4 rb1 = *reinterpret_cast<const float4*>(&s_rz[warp][1][kc * 8 + 4]);
            float2 f;
            f = __bfloat1622float2(*reinterpret_cast<const __nv_bfloat162*>(&gv0.x));
            acc0 = fmaf(ra0.x, f.x, acc0); acc0 = fmaf(ra0.y, f.y, acc0);
            f = __bfloat1622float2(*reinterpret_cast<const __nv_bfloat162*>(&gv0.y));
            acc0 = fmaf(ra0.z, f.x, acc0); acc0 = fmaf(ra0.w, f.y, acc0);
            f = __bfloat1622float2(*reinterpret_cast<const __nv_bfloat162*>(&gv0.z));
            acc0 = fmaf(rb0.x, f.x, acc0); acc0 = fmaf(rb0.y, f.y, acc0);
            f = __bfloat1622float2(*reinterpret_cast<const __nv_bfloat162*>(&gv0.w));
            acc0 = fmaf(rb0.z, f.x, acc0); acc0 = fmaf(rb0.w, f.y, acc0);
            f = __bfloat1622float2(*reinterpret_cast<const __nv_bfloat162*>(&gv1.x));
            acc1 = fmaf(ra1.x, f.x, acc1); acc1 = fmaf(ra1.y, f.y, acc1);
            f = __bfloat1622float2(*reinterpret_cast<const __nv_bfloat162*>(&gv1.y));
            acc1 = fmaf(ra1.z, f.x, acc1); acc1 = fmaf(ra1.w, f.y, acc1);
            f = __bfloat1622float2(*reinterpret_cast<const __nv_bfloat162*>(&gv1.z));
            acc1 = fmaf(rb1.x, f.x, acc1); acc1 = fmaf(rb1.y, f.y, acc1);
            f = __bfloat1622float2(*reinterpret_cast<const __nv_bfloat162*>(&gv1.w));
            acc1 = fmaf(rb1.z, f.x, acc1); acc1 = fmaf(rb1.w, f.y, acc1);
        }

        // stash ef to smem; read back as float4 broadcasts for the coord MLP
        s_ef[warp][0][lane] = acc0;
        s_ef[warp][1][lane] = acc1;
        __syncwarp();

        float t0A = sbc1[lane], t1A = sbc1[32 + lane];
        float t0B = t0A, t1B = t1A;
#pragma unroll
        for (int q = 0; q < 8; q++) {
            float4 eA = *reinterpret_cast<const float4*>(&s_ef[warp][0][q * 4]);
            float4 eB = *reinterpret_cast<const float4*>(&s_ef[warp][1][q * 4]);
            float2 w0 = sWc1p[(q * 4 + 0) * 32 + lane];
            float2 w1 = sWc1p[(q * 4 + 1) * 32 + lane];
            float2 w2 = sWc1p[(q * 4 + 2) * 32 + lane];
            float2 w3 = sWc1p[(q * 4 + 3) * 32 + lane];
            t0A = fmaf(eA.x, w0.x, t0A); t1A = fmaf(eA.x, w0.y, t1A);
            t0B = fmaf(eB.x, w0.x, t0B); t1B = fmaf(eB.x, w0.y, t1B);
            t0A = fmaf(eA.y, w1.x, t0A); t1A = fmaf(eA.y, w1.y, t1A);
            t0B = fmaf(eB.y, w1.x, t0B); t1B = fmaf(eB.y, w1.y, t1B);
            t0A = fmaf(eA.z, w2.x, t0A); t1A = fmaf(eA.z, w2.y, t1A);
            t0B = fmaf(eB.z, w2.x, t0B); t1B = fmaf(eB.z, w2.y, t1B);
            t0A = fmaf(eA.w, w3.x, t0A); t1A = fmaf(eA.w, w3.y, t1A);
            t0B = fmaf(eB.w, w3.x, t0B); t1B = fmaf(eB.w, w3.y, t1B);
        }
        t0A = fmaxf(t0A, 0.f); t1A = fmaxf(t1A, 0.f);
        t0B = fmaxf(t0B, 0.f); t1B = fmaxf(t1B, 0.f);
        float wc2a = sWc2[lane], wc2b = sWc2[32 + lane];
        float pA = fmaf(t0A, wc2a, t1A * wc2b);
        float pB = fmaf(t0B, wc2a, t1B * wc2b);
#pragma unroll
        for (int off = 16; off; off >>= 1) {
            pA += __shfl_xor_sync(FULL, pA, off);
            pB += __shfl_xor_sync(FULL, pB, off);
        }

        atomicAdd(&g_sum_ef[row0 * 32 + lane], acc0);
        if (vB) atomicAdd(&g_sum_ef[row1 * 32 + lane], acc1);
        if (lane < 3) {
            float cdA = g_scd[(size_t)jA * 4 + lane];
            atomicAdd(&g_sum_tr[row0 * 3 + lane], cdA * pA);
            if (vB) {
                float cdB = g_scd[(size_t)jB * 4 + lane];
                atomicAdd(&g_sum_tr[row1 * 3 + lane], cdB * pB);
            }
        }
        __syncwarp();
    }
}

// ---------------- node epilogue ----------------
__global__ void node_kernel(const float* __restrict__ h, const float* __restrict__ coord,
                            const float* __restrict__ root, const float* __restrict__ bias,
                            float* __restrict__ out, int N) {
    int warp = threadIdx.x >> 5, lane = threadIdx.x & 31;
    int n = blockIdx.x * 8 + warp;
    if (n >= N) return;
    float hv = h[n * 32 + lane];
    float inv = 1.f / fmaxf((float)g_cnt[n], 1.f);
    float agg = g_sum_ef[n * 32 + lane] * inv + bias[lane];
#pragma unroll
    for (int i = 0; i < 32; i++)
        agg = fmaf(__shfl_sync(0xffffffffu, hv, i), root[i * 32 + lane], agg);
    out[n * 32 + lane] = hv + fmaxf(agg, 0.f) * 0.25f;
    if (lane < 3)
        out[N * 32 + n * 3 + lane] = g_sum_tr[n * 3 + lane] * inv * 0.25f + coord[n * 3 + lane];
}

extern "C" void kernel_launch(void* const* d_in, const int* in_sizes, int n_in,
                              void* d_out, int out_size) {
    const float* h     = (const float*)d_in[0];
    const int*   ei    = (const int*)  d_in[1];
    const float* coord = (const float*)d_in[2];
    const float* ea    = (const float*)d_in[3];
    const float* Wk1   = (const float*)d_in[4];
    const float* bk1   = (const float*)d_in[5];
    const float* Wk2   = (const float*)d_in[6];
    const float* bk2   = (const float*)d_in[7];
    const float* root  = (const float*)d_in[8];
    const float* bias  = (const float*)d_in[9];
    const float* Wc1   = (const float*)d_in[10];
    const float* bc1   = (const float*)d_in[11];
    const float* Wc2   = (const float*)d_in[12];

    int N = in_sizes[0] / 32;
    int E = in_sizes[1] / 2;
    float* out = (float*)d_out;

    zero_kernel<<<(N * 32 + 255) / 256, 256>>>(N);
    bperm_kernel<<<(4096 * 32 + 255) / 256, 256>>>(Wk2);
    hb_kernel<<<(N + 7) / 8, 256>>>(h, bk2, N);
    dim3 gg((N + 63) / 64, 8);
    g_kernel<<<gg, 256>>>(h, N);
    hist_kernel<<<(E + 255) / 256, 256>>>(ei, E);
    scan_kernel<<<1, 1024>>>(N);
    scatter_kernel<<<(E + 255) / 256, 256>>>(ei, ea, coord, E);
    edge_kernel<<<592, 256>>>(Wk1, bk1, Wc1, bc1, Wc2, E);
    node_kernel<<<(N + 7) / 8, 256>>>(h, coord, root, bias, out, N);
}